// round 10
// baseline (speedup 1.0000x reference)
#include <cuda_runtime.h>
#include <cuda_fp16.h>
#include <stdint.h>

#define N_ROWS   262144
#define TILE_M   128
#define NTHREADS 256
#define SMEM_BYTES 231936

// fp16 weights: W2 [256][128] @0, W3 [128][256] @32768, W4 [512][128] @65536
__device__ __half g_Wh[131072];

__global__ void cvt_weights_kernel(const float* __restrict__ W2,
                                   const float* __restrict__ W3,
                                   const float* __restrict__ W4) {
    int i = blockIdx.x * blockDim.x + threadIdx.x;   // 65536 threads
    if (i < 32768) {
        g_Wh[i]         = __float2half_rn(W2[i]);
        g_Wh[32768 + i] = __float2half_rn(W3[i]);
    }
    g_Wh[65536 + i] = __float2half_rn(W4[i]);
}

__device__ __forceinline__ uint32_t smem_u32(const void* p) {
    return (uint32_t)__cvta_generic_to_shared(p);
}

__device__ __forceinline__ void ldmatrix_x4(uint32_t r[4], uint32_t addr) {
    asm volatile("ldmatrix.sync.aligned.m8n8.x4.shared.b16 {%0,%1,%2,%3}, [%4];\n"
                 : "=r"(r[0]), "=r"(r[1]), "=r"(r[2]), "=r"(r[3]) : "r"(addr));
}

__device__ __forceinline__ void mma16816(float c[4], const uint32_t a[4], uint32_t b0, uint32_t b1) {
    asm volatile("mma.sync.aligned.m16n8k16.row.col.f32.f16.f16.f32 "
                 "{%0,%1,%2,%3},{%4,%5,%6,%7},{%8,%9},{%0,%1,%2,%3};\n"
                 : "+f"(c[0]), "+f"(c[1]), "+f"(c[2]), "+f"(c[3])
                 : "r"(a[0]), "r"(a[1]), "r"(a[2]), "r"(a[3]), "r"(b0), "r"(b1));
}

__device__ __forceinline__ void cp_async16(uint32_t dst_smem, const void* src) {
    asm volatile("cp.async.cg.shared.global [%0], [%1], 16;\n" :: "r"(dst_smem), "l"(src));
}
__device__ __forceinline__ void cp_commit() { asm volatile("cp.async.commit_group;\n"); }
template <int n>
__device__ __forceinline__ void cp_wait() { asm volatile("cp.async.wait_group %0;\n" :: "n"(n)); }

// tanh-GELU in sigmoid form: gelu(x) = x * sigmoid(1.5957691x + 0.0713548x^3)
__device__ __forceinline__ float fast_gelu(float x) {
    float x3 = x * x * x;
    float z  = fmaf(0.0713548162726f, x3, 1.5957691216057308f * x);
    float e  = __expf(-z);
    return __fdividef(x, 1.0f + e);
}

__device__ __forceinline__ uint32_t pack_h2(float a, float b) {
    __half2 h = __floats2half2_rn(a, b);
    return *(uint32_t*)&h;
}

// cp.async a [nrows x K] fp16 dense global tile into swizzled row-major smem:
// addr(row, chunk16) = row*(K*2) + ((chunk16 ^ (row&7)) << 4)
__device__ __forceinline__ void copy_wsw(const __half* __restrict__ src, int nrows, int K,
                                         uint32_t dst, int tid) {
    int nc  = K >> 3;                 // 16B chunks per row
    int RB  = K << 1;                 // row bytes
    int tot = nrows * nc;
    for (int i = tid; i < tot; i += NTHREADS) {
        int r = i / nc, c = i - r * nc;
        cp_async16(dst + (uint32_t)(r * RB + ((c ^ (r & 7)) << 4)), src + r * K + (c << 3));
    }
}

// swizzled byte offset for (row, col) in a region with row-bytes RB (cols are halves)
__device__ __forceinline__ uint32_t swoff(int row, int col, int RB) {
    return (uint32_t)(row * RB + (((col >> 3) ^ (row & 7)) << 4) + ((col & 7) << 1));
}

// SMEM regions:
//  oA @ 0      : 65536  W2  -> W4a
//  oB @ 65536  : 65536  W3
//  oC @ 131072 : 65536  [head 2.5K: sW1+sB1 during L1] -> h2 -> W4b
//  oD @ 196608 : 32768  h1 -> h3
//  smalls @ 229376: sB2 1024, sB3 512, sTok 512, sPad 512  => 231936
#define oA 0
#define oB 65536
#define oC 131072
#define oD 196608

__global__ __launch_bounds__(NTHREADS, 1)
void embedder_kernel(const float* __restrict__ joint_info,
                     const int* __restrict__ joint_token,
                     const float* __restrict__ emb,
                     const float* __restrict__ W1, const float* __restrict__ b1,
                     const float* __restrict__ b2, const float* __restrict__ b3,
                     float* __restrict__ out) {
    extern __shared__ char smem[];
    const uint32_t S = smem_u32(smem);
    float* sW1 = (float*)(smem + oC);            // dead after L1 (h2 overwrites)
    float* sB1 = (float*)(smem + oC + 2048);     // dead after L1
    float* sB2 = (float*)(smem + 229376);
    float* sB3 = (float*)(smem + 230400);
    int*   sTok = (int*)(smem + 230912);
    int*   sPad = (int*)(smem + 231424);

    int tid  = threadIdx.x;
    int lane = tid & 31, warp = tid >> 5;
    int wm = warp >> 2, wn = warp & 3;           // 2M x 4N warp grid
    int R0 = blockIdx.x * TILE_M;

    // ---- prefetch W2 (G0), W3 (G1) ----
    copy_wsw(g_Wh, 256, 128, S + oA, tid);          cp_commit();
    copy_wsw(g_Wh + 32768, 128, 256, S + oB, tid);  cp_commit();

    // ---- small data ----
    int row1 = tid >> 1;                          // L1: 2 threads per row
    float4 x = ((const float4*)joint_info)[R0 + row1];
    if (tid < 128) {
        float4 xx = ((const float4*)joint_info)[R0 + tid];
        sPad[tid] = (xx.x == 0.0f && xx.y == 0.0f && xx.z == 0.0f && xx.w == 0.0f) ? 1 : 0;
        sTok[tid] = joint_token[R0 + tid];
        sB1[tid]  = b1[tid];
        sB3[tid]  = b3[tid];
    }
    sB2[tid] = b2[tid];
    ((float2*)sW1)[tid] = ((const float2*)W1)[tid];   // 512 floats
    __syncthreads();

    // ---- layer 1 (K=4, fp32 exact): 2 threads/row, 64 cols each -> h1 @oD ----
    {
        int half = tid & 1;
        int r7 = row1 & 7;
#pragma unroll
        for (int jc = 0; jc < 8; ++jc) {
            int c16 = half * 8 + jc;
            uint32_t v[4];
#pragma unroll
            for (int j = 0; j < 4; ++j) {
                int c = c16 * 8 + j * 2;
                float4 wa = *(const float4*)&sW1[c * 4];
                float4 wb = *(const float4*)&sW1[(c + 1) * 4];
                float y0 = fmaf(x.x, wa.x, fmaf(x.y, wa.y, fmaf(x.z, wa.z, fmaf(x.w, wa.w, sB1[c]))));
                float y1 = fmaf(x.x, wb.x, fmaf(x.y, wb.y, fmaf(x.z, wb.z, fmaf(x.w, wb.w, sB1[c + 1]))));
                v[j] = pack_h2(fast_gelu(y0), fast_gelu(y1));
            }
            *(uint4*)(smem + oD + row1 * 256 + ((c16 ^ r7) << 4)) = *(uint4*)v;
        }
    }
    cp_wait<1>();        // W2 done (W3 may be in flight)
    __syncthreads();     // h1 + W2 visible

    // per-lane fragment coords
    int g = lane >> 2, t = lane & 3;
    int ri = lane & 7, mi = lane >> 3, sel = mi >> 1;
    int wrow = ri + ((mi & 1) << 3);

    // ================= layer 2: h1[128x128] @ W2[256x128]^T =================
    {
        float acc[4][4][8];
#pragma unroll
        for (int s = 0; s < 4; ++s)
#pragma unroll
            for (int n = 0; n < 4; ++n)
#pragma unroll
                for (int q = 0; q < 8; ++q) acc[s][n][q] = 0.0f;

        uint32_t aRow[4], bRow[4];
#pragma unroll
        for (int s = 0; s < 4; ++s) aRow[s] = S + oD + (64 * wm + 16 * s + wrow) * 256;
#pragma unroll
        for (int n = 0; n < 4; ++n) bRow[n] = S + oA + (64 * wn + 16 * n + wrow) * 256;

#pragma unroll
        for (int kt = 0; kt < 8; ++kt) {
            uint32_t sw = (uint32_t)(((2 * kt + sel) ^ ri) << 4);
            uint32_t A[4][4], B[4][4];
#pragma unroll
            for (int s = 0; s < 4; ++s) ldmatrix_x4(A[s], aRow[s] + sw);
#pragma unroll
            for (int n = 0; n < 4; ++n) ldmatrix_x4(B[n], bRow[n] + sw);
#pragma unroll
            for (int s = 0; s < 4; ++s)
#pragma unroll
                for (int n = 0; n < 4; ++n) {
                    mma16816(acc[s][n] + 0, A[s], B[n][0], B[n][2]);
                    mma16816(acc[s][n] + 4, A[s], B[n][1], B[n][3]);
                }
        }

        // epilogue: +bias, gelu, fp16 -> h2 @oC (RB 512)
#pragma unroll
        for (int n = 0; n < 4; ++n) {
            int c0 = 64 * wn + 16 * n + 2 * t;
            int c1 = c0 + 8;
            float b0 = sB2[c0], b1v = sB2[c0 + 1];
            float b2v = sB2[c1], b3v = sB2[c1 + 1];
#pragma unroll
            for (int s = 0; s < 4; ++s) {
                int rl = 64 * wm + 16 * s + g, rh = rl + 8;
                const float* a = acc[s][n];
                *(uint32_t*)(smem + oC + swoff(rl, c0, 512)) =
                    pack_h2(fast_gelu(a[0] + b0), fast_gelu(a[1] + b1v));
                *(uint32_t*)(smem + oC + swoff(rh, c0, 512)) =
                    pack_h2(fast_gelu(a[2] + b0), fast_gelu(a[3] + b1v));
                *(uint32_t*)(smem + oC + swoff(rl, c1, 512)) =
                    pack_h2(fast_gelu(a[4] + b2v), fast_gelu(a[5] + b3v));
                *(uint32_t*)(smem + oC + swoff(rh, c1, 512)) =
                    pack_h2(fast_gelu(a[6] + b2v), fast_gelu(a[7] + b3v));
            }
        }
    }
    __syncthreads();                                         // W2 reads + h2 writes done
    copy_wsw(g_Wh + 65536, 256, 128, S + oA, tid);  cp_commit();   // G2: W4a -> oA
    cp_wait<1>();                                            // W3 done
    __syncthreads();

    // ================= layer 3: h2[128x256] @ W3[128x256]^T =================
    {
        float acc[4][2][8];
#pragma unroll
        for (int s = 0; s < 4; ++s)
#pragma unroll
            for (int n = 0; n < 2; ++n)
#pragma unroll
                for (int q = 0; q < 8; ++q) acc[s][n][q] = 0.0f;

        uint32_t aRow[4], bRow[2];
#pragma unroll
        for (int s = 0; s < 4; ++s) aRow[s] = S + oC + (64 * wm + 16 * s + wrow) * 512;
#pragma unroll
        for (int n = 0; n < 2; ++n) bRow[n] = S + oB + (32 * wn + 16 * n + wrow) * 512;

#pragma unroll
        for (int kt = 0; kt < 16; ++kt) {
            uint32_t sw = (uint32_t)(((2 * kt + sel) ^ ri) << 4);
            uint32_t A[4][4], B[2][4];
#pragma unroll
            for (int s = 0; s < 4; ++s) ldmatrix_x4(A[s], aRow[s] + sw);
#pragma unroll
            for (int n = 0; n < 2; ++n) ldmatrix_x4(B[n], bRow[n] + sw);
#pragma unroll
            for (int s = 0; s < 4; ++s)
#pragma unroll
                for (int n = 0; n < 2; ++n) {
                    mma16816(acc[s][n] + 0, A[s], B[n][0], B[n][2]);
                    mma16816(acc[s][n] + 4, A[s], B[n][1], B[n][3]);
                }
        }

        // epilogue -> h3 @oD (RB 256)
#pragma unroll
        for (int n = 0; n < 2; ++n) {
            int c0 = 32 * wn + 16 * n + 2 * t;
            int c1 = c0 + 8;
            float b0 = sB3[c0], b1v = sB3[c0 + 1];
            float b2v = sB3[c1], b3v = sB3[c1 + 1];
#pragma unroll
            for (int s = 0; s < 4; ++s) {
                int rl = 64 * wm + 16 * s + g, rh = rl + 8;
                const float* a = acc[s][n];
                *(uint32_t*)(smem + oD + swoff(rl, c0, 256)) =
                    pack_h2(fast_gelu(a[0] + b0), fast_gelu(a[1] + b1v));
                *(uint32_t*)(smem + oD + swoff(rh, c0, 256)) =
                    pack_h2(fast_gelu(a[2] + b0), fast_gelu(a[3] + b1v));
                *(uint32_t*)(smem + oD + swoff(rl, c1, 256)) =
                    pack_h2(fast_gelu(a[4] + b2v), fast_gelu(a[5] + b3v));
                *(uint32_t*)(smem + oD + swoff(rh, c1, 256)) =
                    pack_h2(fast_gelu(a[6] + b2v), fast_gelu(a[7] + b3v));
            }
        }
    }
    __syncthreads();                                         // h2 reads + h3 writes done
    copy_wsw(g_Wh + 98304, 256, 128, S + oC, tid);  cp_commit();   // G3: W4b -> oC
    cp_wait<1>();                                            // W4a done
    __syncthreads();

    // ================= layer 4: h3[128x128] @ W4[512x128]^T (2 halves) =======
#pragma unroll
    for (int h = 0; h < 2; ++h) {
        uint32_t wBase = (h == 0) ? (S + oA) : (S + oC);
        float acc[4][4][8];
#pragma unroll
        for (int s = 0; s < 4; ++s)
#pragma unroll
            for (int n = 0; n < 4; ++n)
#pragma unroll
                for (int q = 0; q < 8; ++q) acc[s][n][q] = 0.0f;

        uint32_t aRow[4], bRow[4];
#pragma unroll
        for (int s = 0; s < 4; ++s) aRow[s] = S + oD + (64 * wm + 16 * s + wrow) * 256;
#pragma unroll
        for (int n = 0; n < 4; ++n) bRow[n] = wBase + (64 * wn + 16 * n + wrow) * 256;

#pragma unroll
        for (int kt = 0; kt < 8; ++kt) {
            uint32_t sw = (uint32_t)(((2 * kt + sel) ^ ri) << 4);
            uint32_t A[4][4], B[4][4];
#pragma unroll
            for (int s = 0; s < 4; ++s) ldmatrix_x4(A[s], aRow[s] + sw);
#pragma unroll
            for (int n = 0; n < 4; ++n) ldmatrix_x4(B[n], bRow[n] + sw);
#pragma unroll
            for (int s = 0; s < 4; ++s)
#pragma unroll
                for (int n = 0; n < 4; ++n) {
                    mma16816(acc[s][n] + 0, A[s], B[n][0], B[n][2]);
                    mma16816(acc[s][n] + 4, A[s], B[n][1], B[n][3]);
                }
        }

        // epilogue: emb add + pad override, direct STG
#pragma unroll
        for (int s = 0; s < 4; ++s) {
            int rl = 64 * wm + 16 * s + g, rh = rl + 8;
            int pl = sPad[rl], ph = sPad[rh];
            const float* el = emb + (pl ? 0 : sTok[rl]) * 512;
            const float* eh = emb + (ph ? 0 : sTok[rh]) * 512;
            float* ol = out + (size_t)(R0 + rl) * 512;
            float* oh = out + (size_t)(R0 + rh) * 512;
#pragma unroll
            for (int n = 0; n < 4; ++n) {
                int cc0 = 256 * h + 64 * wn + 16 * n + 2 * t;
                int cc1 = cc0 + 8;
                const float* a = acc[s][n];
                float2 e, o;
                e = *(const float2*)(el + cc0);
                o.x = pl ? e.x : (a[0] + e.x);  o.y = pl ? e.y : (a[1] + e.y);
                *(float2*)(ol + cc0) = o;
                e = *(const float2*)(eh + cc0);
                o.x = ph ? e.x : (a[2] + e.x);  o.y = ph ? e.y : (a[3] + e.y);
                *(float2*)(oh + cc0) = o;
                e = *(const float2*)(el + cc1);
                o.x = pl ? e.x : (a[4] + e.x);  o.y = pl ? e.y : (a[5] + e.y);
                *(float2*)(ol + cc1) = o;
                e = *(const float2*)(eh + cc1);
                o.x = ph ? e.x : (a[6] + e.x);  o.y = ph ? e.y : (a[7] + e.y);
                *(float2*)(oh + cc1) = o;
            }
        }
        if (h == 0) {
            cp_wait<0>();        // W4b ready
            __syncthreads();
        }
    }
}

extern "C" void kernel_launch(void* const* d_in, const int* in_sizes, int n_in,
                              void* d_out, int out_size) {
    const float* joint_info  = (const float*)d_in[0];
    const int*   joint_token = (const int*)d_in[1];
    const float* emb         = (const float*)d_in[2];
    const float* W1          = (const float*)d_in[3];
    const float* b1          = (const float*)d_in[4];
    const float* W2          = (const float*)d_in[5];
    const float* b2          = (const float*)d_in[6];
    const float* W3          = (const float*)d_in[7];
    const float* b3          = (const float*)d_in[8];
    const float* W4          = (const float*)d_in[9];

    cvt_weights_kernel<<<256, 256>>>(W2, W3, W4);

    cudaFuncSetAttribute(embedder_kernel,
                         cudaFuncAttributeMaxDynamicSharedMemorySize, SMEM_BYTES);
    embedder_kernel<<<N_ROWS / TILE_M, NTHREADS, SMEM_BYTES>>>(
        joint_info, joint_token, emb, W1, b1, b2, b3, (float*)d_out);
}